// round 13
// baseline (speedup 1.0000x reference)
#include <cuda_runtime.h>
#include <cuda_bf16.h>
#include <math.h>
#include <stdint.h>

#define NROWS 8192
#define DDIM  256
#define MARGIN 0.3f

#define BM 128
#define BN 128
#define KC  32
#define NSTAGE (DDIM / KC)   // 8
#define NPIPE 3              // smem ring stages

// ---- dynamic smem layout ----
#define OFF_SQA 0
#define OFF_TA  512
#define OFF_SQB 1024
#define OFF_TB  1536
#define OFF_APR 2048
#define OFF_ANR 2560
#define OFF_APC 3072
#define OFF_ANC 3584
#define OFF_TILE 4096
// per stage: A tile 128 rows x 128B (hi chunks 0-3, lo chunks 4-7) = 16KB, B same
#define STAGE_BYTES 32768
#define A_OFF 0
#define B_OFF 16384
#define SMEM_TOTAL (OFF_TILE + NPIPE * STAGE_BYTES)   // 102400 -> 2 CTAs/SM

// ---- device globals (no allocation allowed) ----
__device__ float        g_sq[NROWS];
__device__ unsigned int g_ap[NROWS];
__device__ unsigned int g_an[NROWS];
__device__ int          g_tgt[NROWS];
__device__ int          g_is32;
__device__ uint4        g_xhi4[NROWS * DDIM / 8];   // bf16 hi, 8 per uint4
__device__ uint4        g_xlo4[NROWS * DDIM / 8];   // bf16 lo

// ---- helpers ----
static __device__ __forceinline__ uint32_t smem_u32(const void* p) {
    uint32_t a;
    asm("{ .reg .u64 t; cvta.to.shared.u64 t, %1; cvt.u32.u64 %0, t; }" : "=r"(a) : "l"(p));
    return a;
}
static __device__ __forceinline__ void cp16(uint32_t saddr, const void* g) {
    asm volatile("cp.async.cg.shared.global [%0], [%1], 16;" :: "r"(saddr), "l"(g));
}
#define CP_COMMIT() asm volatile("cp.async.commit_group;" ::: "memory")
#define CP_WAIT(n)  asm volatile("cp.async.wait_group %0;" :: "n"(n) : "memory")

static __device__ __forceinline__ void ldsm4(uint32_t a, uint32_t* r) {
    asm volatile("ldmatrix.sync.aligned.m8n8.x4.shared.b16 {%0,%1,%2,%3}, [%4];"
                 : "=r"(r[0]), "=r"(r[1]), "=r"(r[2]), "=r"(r[3]) : "r"(a));
}
static __device__ __forceinline__ void mma16816(float* d, const uint32_t* a, const uint32_t* b) {
    asm volatile("mma.sync.aligned.m16n8k16.row.col.f32.bf16.bf16.f32 "
                 "{%0,%1,%2,%3}, {%4,%5,%6,%7}, {%8,%9}, {%0,%1,%2,%3};"
                 : "+f"(d[0]), "+f"(d[1]), "+f"(d[2]), "+f"(d[3])
                 : "r"(a[0]), "r"(a[1]), "r"(a[2]), "r"(a[3]), "r"(b[0]), "r"(b[1]));
}
// swizzled byte offset: tile rows of 128B, chunk (16B) index 0-7 XOR (row&7)
static __device__ __forceinline__ uint32_t swz(int r, int chunk) {
    return (uint32_t)((r << 7) + ((chunk ^ (r & 7)) << 4));
}

// ---------------------------------------------------------------------------
__global__ void init_kernel() { g_is32 = 0; }

// norms + reduction init + dtype detect + bf16 hi/lo split
__global__ void prep_kernel(const float* __restrict__ x, const int* __restrict__ t32)
{
    int row  = blockIdx.x * 8 + (threadIdx.x >> 5);
    int lane = threadIdx.x & 31;
    const float* xr = x + (size_t)row * DDIM;
    __nv_bfloat16* xh = (__nv_bfloat16*)g_xhi4;
    __nv_bfloat16* xl = (__nv_bfloat16*)g_xlo4;
    float s = 0.f;
#pragma unroll
    for (int k = lane; k < DDIM; k += 32) {
        float v = xr[k];
        s = fmaf(v, v, s);
        __nv_bfloat16 hi = __float2bfloat16(v);
        float lo = v - __bfloat162float(hi);
        xh[(size_t)row * DDIM + k] = hi;
        xl[(size_t)row * DDIM + k] = __float2bfloat16(lo);
    }
#pragma unroll
    for (int o = 16; o; o >>= 1) s += __shfl_xor_sync(0xffffffffu, s, o);
    if (lane == 0) {
        g_sq[row] = s;
        g_ap[row] = 0u;
        g_an[row] = 0x7f800000u;
        if (row < 2048 && t32[2 * row + 1] != 0) atomicOr(&g_is32, 1);
    }
}

__global__ void convert_kernel(const void* __restrict__ tgt)
{
    int i = blockIdx.x * 256 + threadIdx.x;
    if (i < NROWS) {
        if (g_is32) g_tgt[i] = ((const int*)tgt)[i];
        else        g_tgt[i] = (int)((const long long*)tgt)[i];
    }
}

// ---------------------------------------------------------------------------
// Fused HMMA (mma.sync bf16 hi/lo) GEMM tile + dist + dual row/col reductions.
// Upper-triangular blocks only; 3-stage cp.async ring, ONE barrier per stage.
// ---------------------------------------------------------------------------
__global__ __launch_bounds__(256, 2)
void tile_kernel()
{
    const int bx = blockIdx.x;
    const int by = blockIdx.y;
    if (by > bx) return;
    const bool diag = (bx == by);

    extern __shared__ char sm[];
    const uint32_t sb = smem_u32(sm);

    const int tid  = threadIdx.x;
    const int lane = tid & 31;
    const int wid  = tid >> 5;
    const int wm   = wid & 1;     // 2 warps over M (64 rows each)
    const int wn   = wid >> 1;    // 4 warps over N (32 cols each)
    const int r0   = by * BM;
    const int c0   = bx * BN;

    // per-thread load mapping (8 cp16/thread per stage: 4 A + 4 B)
    // idx = tid + t*256 ; r = idx>>3 ; c8 = idx&7 (0-3 hi, 4-7 lo)

    // ---- prologue: issue stages 0 and 1 ----
#pragma unroll
    for (int s = 0; s < 2; s++) {
        uint32_t base = sb + OFF_TILE + s * STAGE_BYTES;
        const int kb = s * (KC / 8);
#pragma unroll
        for (int t = 0; t < 4; t++) {
            int idx = tid + t * 256;
            int r = idx >> 3, c8 = idx & 7;
            uint32_t so = swz(r, c8);
            const uint4* srcA = (c8 < 4) ? &g_xhi4[(r0 + r) * (DDIM / 8) + kb + c8]
                                         : &g_xlo4[(r0 + r) * (DDIM / 8) + kb + (c8 - 4)];
            const uint4* srcB = (c8 < 4) ? &g_xhi4[(c0 + r) * (DDIM / 8) + kb + c8]
                                         : &g_xlo4[(c0 + r) * (DDIM / 8) + kb + (c8 - 4)];
            cp16(base + A_OFF + so, srcA);
            cp16(base + B_OFF + so, srcB);
        }
        CP_COMMIT();
    }

    // ---- metadata into smem ----
    if (tid < 128) {
        ((float*)(sm + OFF_SQA))[tid]    = g_sq[r0 + tid];
        ((int*)(sm + OFF_TA))[tid]       = g_tgt[r0 + tid];
        ((float*)(sm + OFF_SQB))[tid]    = g_sq[c0 + tid];
        ((int*)(sm + OFF_TB))[tid]       = g_tgt[c0 + tid];
        ((uint32_t*)(sm + OFF_APR))[tid] = 0u;
        ((uint32_t*)(sm + OFF_ANR))[tid] = 0x7f800000u;
        ((uint32_t*)(sm + OFF_APC))[tid] = 0u;
        ((uint32_t*)(sm + OFF_ANC))[tid] = 0x7f800000u;
    }

    float acc[4][4][4];
#pragma unroll
    for (int i = 0; i < 4; i++)
#pragma unroll
        for (int j = 0; j < 4; j++)
#pragma unroll
            for (int q = 0; q < 4; q++) acc[i][j][q] = 0.f;

    // ---- mainloop: 8 K chunks, 3-stage ring, one barrier per stage ----
    int bufc = 0;                 // (s % 3)
    int bufp = 2;                 // ((s+2) % 3)
#pragma unroll 1
    for (int s = 0; s < NSTAGE; s++) {
        if (s == NSTAGE - 1) { CP_WAIT(0); } else { CP_WAIT(1); }
        __syncthreads();

        // prefetch stage s+2 into buf (s+2)%3 (consumed at stage s-1; safe past barrier)
        if (s + 2 < NSTAGE) {
            const int sn = s + 2;
            uint32_t base = sb + OFF_TILE + bufp * STAGE_BYTES;
            const int kb = sn * (KC / 8);
#pragma unroll
            for (int t = 0; t < 4; t++) {
                int idx = tid + t * 256;
                int r = idx >> 3, c8 = idx & 7;
                uint32_t so = swz(r, c8);
                const uint4* srcA = (c8 < 4) ? &g_xhi4[(r0 + r) * (DDIM / 8) + kb + c8]
                                             : &g_xlo4[(r0 + r) * (DDIM / 8) + kb + (c8 - 4)];
                const uint4* srcB = (c8 < 4) ? &g_xhi4[(c0 + r) * (DDIM / 8) + kb + c8]
                                             : &g_xlo4[(c0 + r) * (DDIM / 8) + kb + (c8 - 4)];
                cp16(base + A_OFF + so, srcA);
                cp16(base + B_OFF + so, srcB);
            }
            CP_COMMIT();
        }

        const uint32_t base = sb + OFF_TILE + bufc * STAGE_BYTES;
#pragma unroll
        for (int st = 0; st < 2; st++) {      // 2 k-steps of 16 per chunk
            const int k0 = st * 16;
            uint32_t bh[2][4], bl[2][4];
            const int rB0 = wn * 32 + ((lane >> 4) << 3) + (lane & 7);
            const int cB  = (k0 + (((lane >> 3) & 1) << 3)) >> 3;
#pragma unroll
            for (int jp = 0; jp < 2; jp++) {
                int r = rB0 + jp * 16;
                ldsm4(base + B_OFF + swz(r, cB),     bh[jp]);
                ldsm4(base + B_OFF + swz(r, cB + 4), bl[jp]);
            }
            const int rA0 = wm * 64 + (lane & 15);
            const int cA  = (k0 + ((lane >> 4) << 3)) >> 3;
#pragma unroll
            for (int i = 0; i < 4; i++) {
                uint32_t ah[4], al[4];
                int r = rA0 + i * 16;
                ldsm4(base + A_OFF + swz(r, cA),     ah);
                ldsm4(base + A_OFF + swz(r, cA + 4), al);
#pragma unroll
                for (int j = 0; j < 4; j++) {
                    const uint32_t* bhp = &bh[j >> 1][(j & 1) * 2];
                    const uint32_t* blp = &bl[j >> 1][(j & 1) * 2];
                    mma16816(acc[i][j], ah, bhp);   // hi*hi
                    mma16816(acc[i][j], ah, blp);   // hi*lo
                    mma16816(acc[i][j], al, bhp);   // lo*hi
                }
            }
        }
        bufc = (bufc == 2) ? 0 : bufc + 1;
        bufp = (bufp == 2) ? 0 : bufp + 1;
    }

    // ---- epilogue ----
    const int gid = lane >> 2;
    const int tg  = lane & 3;
    const float* sqA = (const float*)(sm + OFF_SQA);
    const float* sqB = (const float*)(sm + OFF_SQB);
    const int*   tA  = (const int*)(sm + OFF_TA);
    const int*   tB  = (const int*)(sm + OFF_TB);

    float apR[8], anR[8], apC[8], anC[8];
#pragma unroll
    for (int q = 0; q < 8; q++) { apR[q] = 0.f; anR[q] = INFINITY; apC[q] = 0.f; anC[q] = INFINITY; }

#pragma unroll
    for (int i = 0; i < 4; i++) {
#pragma unroll
        for (int h = 0; h < 2; h++) {
            const int r   = wm * 64 + i * 16 + h * 8 + gid;
            const float sqr = sqA[r];
            const int   tr  = tA[r];
#pragma unroll
            for (int j = 0; j < 4; j++) {
#pragma unroll
                for (int e = 0; e < 2; e++) {
                    const int c   = wn * 32 + j * 8 + 2 * tg + e;
                    float dot  = acc[i][j][h * 2 + e];
                    float d2   = sqr + sqB[c] - 2.f * dot;
                    float dist = sqrtf(fmaxf(d2, 1e-12f));
                    if (tr == tB[c]) {
                        apR[i * 2 + h] = fmaxf(apR[i * 2 + h], dist);
                        apC[j * 2 + e] = fmaxf(apC[j * 2 + e], dist);
                    } else {
                        anR[i * 2 + h] = fminf(anR[i * 2 + h], dist);
                        anC[j * 2 + e] = fminf(anC[j * 2 + e], dist);
                    }
                }
            }
        }
    }

    // row-side: reduce over tg (lanes xor 1,2), then smem atomic per row
#pragma unroll
    for (int q = 0; q < 8; q++) {
#pragma unroll
        for (int o = 1; o <= 2; o <<= 1) {
            apR[q] = fmaxf(apR[q], __shfl_xor_sync(0xffffffffu, apR[q], o));
            anR[q] = fminf(anR[q], __shfl_xor_sync(0xffffffffu, anR[q], o));
        }
        if (tg == 0) {
            const int i = q >> 1, h = q & 1;
            const int r = wm * 64 + i * 16 + h * 8 + gid;
            atomicMax((unsigned int*)(sm + OFF_APR) + r, __float_as_uint(apR[q]));
            atomicMin((unsigned int*)(sm + OFF_ANR) + r, __float_as_uint(anR[q]));
        }
    }
    // col-side: reduce over gid (lanes xor 4,8,16), then smem atomic per col
#pragma unroll
    for (int q = 0; q < 8; q++) {
#pragma unroll
        for (int o = 4; o <= 16; o <<= 1) {
            apC[q] = fmaxf(apC[q], __shfl_xor_sync(0xffffffffu, apC[q], o));
            anC[q] = fminf(anC[q], __shfl_xor_sync(0xffffffffu, anC[q], o));
        }
        if (gid == 0) {
            const int j = q >> 1, e = q & 1;
            const int c = wn * 32 + j * 8 + 2 * tg + e;
            atomicMax((unsigned int*)(sm + OFF_APC) + c, __float_as_uint(apC[q]));
            atomicMin((unsigned int*)(sm + OFF_ANC) + c, __float_as_uint(anC[q]));
        }
    }
    __syncthreads();

    if (tid < 128) {
        atomicMax(&g_ap[r0 + tid], ((unsigned int*)(sm + OFF_APR))[tid]);
        atomicMin(&g_an[r0 + tid], ((unsigned int*)(sm + OFF_ANR))[tid]);
        if (!diag) {
            atomicMax(&g_ap[c0 + tid], ((unsigned int*)(sm + OFF_APC))[tid]);
            atomicMin(&g_an[c0 + tid], ((unsigned int*)(sm + OFF_ANC))[tid]);
        }
    }
}

// ---------------------------------------------------------------------------
__global__ void final_kernel(float* __restrict__ out, int out_size)
{
    __shared__ float sl[256];
    __shared__ float sp[256];
    int tid = threadIdx.x;
    float loss = 0.f, prec = 0.f;
    for (int r = tid; r < NROWS; r += 256) {
        float ap = __uint_as_float(g_ap[r]);
        float an = __uint_as_float(g_an[r]);
        loss += fmaxf(ap - an + MARGIN, 0.f);
        prec += (an > ap) ? 1.f : 0.f;
    }
    sl[tid] = loss;
    sp[tid] = prec;
    __syncthreads();
    for (int s = 128; s; s >>= 1) {
        if (tid < s) { sl[tid] += sl[tid + s]; sp[tid] += sp[tid + s]; }
        __syncthreads();
    }
    if (tid == 0) {
        out[0] = sl[0] * (1.0f / NROWS);
        if (out_size > 1) out[1] = sp[0] * (1.0f / NROWS);
    }
}

// ---------------------------------------------------------------------------
extern "C" void kernel_launch(void* const* d_in, const int* in_sizes, int n_in,
                              void* d_out, int out_size)
{
    const float* x   = (const float*)d_in[0];
    const void*  tgt = d_in[1];
    float*       out = (float*)d_out;

    cudaFuncSetAttribute(tile_kernel, cudaFuncAttributeMaxDynamicSharedMemorySize, SMEM_TOTAL);

    init_kernel<<<1, 1>>>();
    prep_kernel<<<NROWS / 8, 256>>>(x, (const int*)tgt);
    convert_kernel<<<NROWS / 256, 256>>>(tgt);

    dim3 grid(NROWS / BN, NROWS / BM);   // (64, 64); lower triangle exits early
    tile_kernel<<<grid, 256, SMEM_TOTAL>>>();

    final_kernel<<<1, 256>>>(out, out_size);
}

// round 15
// speedup vs baseline: 1.3986x; 1.3986x over previous
#include <cuda_runtime.h>
#include <cuda_fp16.h>
#include <math.h>
#include <stdint.h>

#define NROWS 8192
#define DDIM  256
#define MARGIN 0.3f

#define BM 128
#define BN 128
#define KC  64
#define NSTAGE (DDIM / KC)   // 4

// ---- dynamic smem layout ----
#define OFF_SQA 0
#define OFF_TA  512
#define OFF_SQB 1024
#define OFF_TB  1536
#define OFF_APR 2048
#define OFF_ANR 2560
#define OFF_APC 3072
#define OFF_ANC 3584
#define OFF_TILE 4096
// per stage: A-hi 128 rows x 128B = 16KB ; B 128 rows x 256B (hi|lo halves) = 32KB
#define STAGE_BYTES 49152
#define A_OFF 0
#define B_OFF 16384
#define SMEM_TOTAL (OFF_TILE + 2 * STAGE_BYTES)   // 102400 -> 2 CTAs/SM

// ---- device globals (no allocation allowed) ----
__device__ float        g_sq[NROWS];
__device__ unsigned int g_ap[NROWS];
__device__ unsigned int g_an[NROWS];
__device__ int          g_tgt[NROWS];
__device__ int          g_is32;
__device__ uint4        g_xhi4[NROWS * DDIM / 8];   // fp16 hi, 8 per uint4
__device__ uint4        g_xlo4[NROWS * DDIM / 8];   // fp16 lo

// ---- helpers ----
static __device__ __forceinline__ uint32_t smem_u32(const void* p) {
    uint32_t a;
    asm("{ .reg .u64 t; cvta.to.shared.u64 t, %1; cvt.u32.u64 %0, t; }" : "=r"(a) : "l"(p));
    return a;
}
static __device__ __forceinline__ void cp16(uint32_t saddr, const void* g) {
    asm volatile("cp.async.cg.shared.global [%0], [%1], 16;" :: "r"(saddr), "l"(g));
}
#define CP_COMMIT() asm volatile("cp.async.commit_group;" ::: "memory")
#define CP_WAIT(n)  asm volatile("cp.async.wait_group %0;" :: "n"(n) : "memory")

static __device__ __forceinline__ void ldsm4(uint32_t a, uint32_t* r) {
    asm volatile("ldmatrix.sync.aligned.m8n8.x4.shared.b16 {%0,%1,%2,%3}, [%4];"
                 : "=r"(r[0]), "=r"(r[1]), "=r"(r[2]), "=r"(r[3]) : "r"(a));
}
static __device__ __forceinline__ void mma16816(float* d, const uint32_t* a, const uint32_t* b) {
    asm volatile("mma.sync.aligned.m16n8k16.row.col.f32.f16.f16.f32 "
                 "{%0,%1,%2,%3}, {%4,%5,%6,%7}, {%8,%9}, {%0,%1,%2,%3};"
                 : "+f"(d[0]), "+f"(d[1]), "+f"(d[2]), "+f"(d[3])
                 : "r"(a[0]), "r"(a[1]), "r"(a[2]), "r"(a[3]), "r"(b[0]), "r"(b[1]));
}
// A swizzle: 128B rows, 16B chunk index 0-7 XOR (row&7)
static __device__ __forceinline__ uint32_t swzA(int r, int chunk) {
    return (uint32_t)((r << 7) + ((chunk ^ (r & 7)) << 4));
}
// B swizzle: 256B rows (hi half at +0, lo at +128); chunk 0-7 within each half
static __device__ __forceinline__ uint32_t swzB(int r, int chunk) {
    return (uint32_t)((r << 8) + ((chunk ^ (r & 7)) << 4));
}

// ---------------------------------------------------------------------------
__global__ void init_kernel() { g_is32 = 0; }

// norms + reduction init + dtype detect + fp16 hi/lo split
__global__ void prep_kernel(const float* __restrict__ x, const int* __restrict__ t32)
{
    int row  = blockIdx.x * 8 + (threadIdx.x >> 5);
    int lane = threadIdx.x & 31;
    const float* xr = x + (size_t)row * DDIM;
    __half* xh = (__half*)g_xhi4;
    __half* xl = (__half*)g_xlo4;
    float s = 0.f;
#pragma unroll
    for (int k = lane; k < DDIM; k += 32) {
        float v = xr[k];
        s = fmaf(v, v, s);
        __half hi = __float2half_rn(v);
        float lo = v - __half2float(hi);
        xh[(size_t)row * DDIM + k] = hi;
        xl[(size_t)row * DDIM + k] = __float2half_rn(lo);
    }
#pragma unroll
    for (int o = 16; o; o >>= 1) s += __shfl_xor_sync(0xffffffffu, s, o);
    if (lane == 0) {
        g_sq[row] = s;
        g_ap[row] = 0u;
        g_an[row] = 0x7f800000u;
        if (row < 2048 && t32[2 * row + 1] != 0) atomicOr(&g_is32, 1);
    }
}

__global__ void convert_kernel(const void* __restrict__ tgt)
{
    int i = blockIdx.x * 256 + threadIdx.x;
    if (i < NROWS) {
        if (g_is32) g_tgt[i] = ((const int*)tgt)[i];
        else        g_tgt[i] = (int)((const long long*)tgt)[i];
    }
}

// ---------------------------------------------------------------------------
// Fused HMMA (mma.sync fp16 hi/lo, 2 products) + dist + dual row/col reduction.
// Upper-triangular blocks only; cp.async double-buffered; KC=64.
// ---------------------------------------------------------------------------
__global__ __launch_bounds__(256, 2)
void tile_kernel()
{
    const int bx = blockIdx.x;
    const int by = blockIdx.y;
    if (by > bx) return;
    const bool diag = (bx == by);

    extern __shared__ char sm[];
    const uint32_t sb = smem_u32(sm);

    const int tid  = threadIdx.x;
    const int lane = tid & 31;
    const int wid  = tid >> 5;
    const int wm   = wid & 1;     // 2 warps over M (64 rows each)
    const int wn   = wid >> 1;    // 4 warps over N (32 cols each)
    const int r0   = by * BM;
    const int c0   = bx * BN;

    // ---- stage loader: 12 cp16/thread (4 A-hi, 4 B-hi, 4 B-lo) ----
    // idx = tid + t*256 ; r = idx>>3 ; c = idx&7
    {
        const int s = 0;
        uint32_t base = sb + OFF_TILE;
#pragma unroll
        for (int t = 0; t < 4; t++) {
            int idx = tid + t * 256;
            int r = idx >> 3, c = idx & 7;
            cp16(base + A_OFF + swzA(r, c), &g_xhi4[(r0 + r) * (DDIM / 8) + s * 8 + c]);
            uint32_t bo = base + B_OFF + swzB(r, c);
            cp16(bo,       &g_xhi4[(c0 + r) * (DDIM / 8) + s * 8 + c]);
            cp16(bo + 128, &g_xlo4[(c0 + r) * (DDIM / 8) + s * 8 + c]);
        }
        CP_COMMIT();
    }

    // ---- metadata into smem ----
    if (tid < 128) {
        ((float*)(sm + OFF_SQA))[tid]    = g_sq[r0 + tid];
        ((int*)(sm + OFF_TA))[tid]       = g_tgt[r0 + tid];
        ((float*)(sm + OFF_SQB))[tid]    = g_sq[c0 + tid];
        ((int*)(sm + OFF_TB))[tid]       = g_tgt[c0 + tid];
        ((uint32_t*)(sm + OFF_APR))[tid] = 0u;
        ((uint32_t*)(sm + OFF_ANR))[tid] = 0x7f800000u;
        ((uint32_t*)(sm + OFF_APC))[tid] = 0u;
        ((uint32_t*)(sm + OFF_ANC))[tid] = 0x7f800000u;
    }

    float acc[4][4][4];
#pragma unroll
    for (int i = 0; i < 4; i++)
#pragma unroll
        for (int j = 0; j < 4; j++)
#pragma unroll
            for (int q = 0; q < 4; q++) acc[i][j][q] = 0.f;

    // ---- mainloop over 4 K chunks of 64 ----
#pragma unroll 1
    for (int s = 0; s < NSTAGE; s++) {
        if (s + 1 < NSTAGE) {
            const int sn = s + 1;
            uint32_t base = sb + OFF_TILE + (sn & 1) * STAGE_BYTES;
#pragma unroll
            for (int t = 0; t < 4; t++) {
                int idx = tid + t * 256;
                int r = idx >> 3, c = idx & 7;
                cp16(base + A_OFF + swzA(r, c), &g_xhi4[(r0 + r) * (DDIM / 8) + sn * 8 + c]);
                uint32_t bo = base + B_OFF + swzB(r, c);
                cp16(bo,       &g_xhi4[(c0 + r) * (DDIM / 8) + sn * 8 + c]);
                cp16(bo + 128, &g_xlo4[(c0 + r) * (DDIM / 8) + sn * 8 + c]);
            }
            CP_COMMIT();
            CP_WAIT(1);
        } else {
            CP_WAIT(0);
        }
        __syncthreads();

        const uint32_t base = sb + OFF_TILE + (s & 1) * STAGE_BYTES;
#pragma unroll
        for (int st = 0; st < 4; st++) {      // 4 k-steps of 16 per chunk
            // B fragments (hi + lo)
            uint32_t bh[2][4], bl[2][4];
            const int rB0 = wn * 32 + ((lane >> 4) << 3) + (lane & 7);
            const int cB  = st * 2 + ((lane >> 3) & 1);
#pragma unroll
            for (int jp = 0; jp < 2; jp++) {
                uint32_t bo = base + B_OFF + swzB(rB0 + jp * 16, cB);
                ldsm4(bo,       bh[jp]);
                ldsm4(bo + 128, bl[jp]);
            }
            // A fragments (hi only) + MMAs
            const int rA0 = wm * 64 + (lane & 15);
            const int cA  = st * 2 + (lane >> 4);
#pragma unroll
            for (int i = 0; i < 4; i++) {
                uint32_t ah[4];
                ldsm4(base + A_OFF + swzA(rA0 + i * 16, cA), ah);
#pragma unroll
                for (int j = 0; j < 4; j++) {
                    mma16816(acc[i][j], ah, &bh[j >> 1][(j & 1) * 2]);   // hi*hi
                    mma16816(acc[i][j], ah, &bl[j >> 1][(j & 1) * 2]);   // hi*lo
                }
            }
        }
        __syncthreads();
    }

    // ---- epilogue ----
    const int gid = lane >> 2;
    const int tg  = lane & 3;
    const float* sqA = (const float*)(sm + OFF_SQA);
    const float* sqB = (const float*)(sm + OFF_SQB);
    const int*   tA  = (const int*)(sm + OFF_TA);
    const int*   tB  = (const int*)(sm + OFF_TB);

    float apR[8], anR[8], apC[8], anC[8];
#pragma unroll
    for (int q = 0; q < 8; q++) { apR[q] = 0.f; anR[q] = INFINITY; apC[q] = 0.f; anC[q] = INFINITY; }

#pragma unroll
    for (int i = 0; i < 4; i++) {
#pragma unroll
        for (int h = 0; h < 2; h++) {
            const int r   = wm * 64 + i * 16 + h * 8 + gid;
            const float sqr = sqA[r];
            const int   tr  = tA[r];
#pragma unroll
            for (int j = 0; j < 4; j++) {
#pragma unroll
                for (int e = 0; e < 2; e++) {
                    const int c   = wn * 32 + j * 8 + 2 * tg + e;
                    float dot  = acc[i][j][h * 2 + e];
                    float d2   = sqr + sqB[c] - 2.f * dot;
                    float dist = sqrtf(fmaxf(d2, 1e-12f));
                    if (tr == tB[c]) {
                        apR[i * 2 + h] = fmaxf(apR[i * 2 + h], dist);
                        apC[j * 2 + e] = fmaxf(apC[j * 2 + e], dist);
                    } else {
                        anR[i * 2 + h] = fminf(anR[i * 2 + h], dist);
                        anC[j * 2 + e] = fminf(anC[j * 2 + e], dist);
                    }
                }
            }
        }
    }

    // row-side: reduce over tg (lanes xor 1,2), then smem atomic per row
#pragma unroll
    for (int q = 0; q < 8; q++) {
#pragma unroll
        for (int o = 1; o <= 2; o <<= 1) {
            apR[q] = fmaxf(apR[q], __shfl_xor_sync(0xffffffffu, apR[q], o));
            anR[q] = fminf(anR[q], __shfl_xor_sync(0xffffffffu, anR[q], o));
        }
        if (tg == 0) {
            const int i = q >> 1, h = q & 1;
            const int r = wm * 64 + i * 16 + h * 8 + gid;
            atomicMax((unsigned int*)(sm + OFF_APR) + r, __float_as_uint(apR[q]));
            atomicMin((unsigned int*)(sm + OFF_ANR) + r, __float_as_uint(anR[q]));
        }
    }
    // col-side: reduce over gid (lanes xor 4,8,16), then smem atomic per col
#pragma unroll
    for (int q = 0; q < 8; q++) {
#pragma unroll
        for (int o = 4; o <= 16; o <<= 1) {
            apC[q] = fmaxf(apC[q], __shfl_xor_sync(0xffffffffu, apC[q], o));
            anC[q] = fminf(anC[q], __shfl_xor_sync(0xffffffffu, anC[q], o));
        }
        if (gid == 0) {
            const int j = q >> 1, e = q & 1;
            const int c = wn * 32 + j * 8 + 2 * tg + e;
            atomicMax((unsigned int*)(sm + OFF_APC) + c, __float_as_uint(apC[q]));
            atomicMin((unsigned int*)(sm + OFF_ANC) + c, __float_as_uint(anC[q]));
        }
    }
    __syncthreads();

    if (tid < 128) {
        atomicMax(&g_ap[r0 + tid], ((unsigned int*)(sm + OFF_APR))[tid]);
        atomicMin(&g_an[r0 + tid], ((unsigned int*)(sm + OFF_ANR))[tid]);
        if (!diag) {
            atomicMax(&g_ap[c0 + tid], ((unsigned int*)(sm + OFF_APC))[tid]);
            atomicMin(&g_an[c0 + tid], ((unsigned int*)(sm + OFF_ANC))[tid]);
        }
    }
}

// ---------------------------------------------------------------------------
__global__ void final_kernel(float* __restrict__ out, int out_size)
{
    __shared__ float sl[256];
    __shared__ float sp[256];
    int tid = threadIdx.x;
    float loss = 0.f, prec = 0.f;
    for (int r = tid; r < NROWS; r += 256) {
        float ap = __uint_as_float(g_ap[r]);
        float an = __uint_as_float(g_an[r]);
        loss += fmaxf(ap - an + MARGIN, 0.f);
        prec += (an > ap) ? 1.f : 0.f;
    }
    sl[tid] = loss;
    sp[tid] = prec;
    __syncthreads();
    for (int s = 128; s; s >>= 1) {
        if (tid < s) { sl[tid] += sl[tid + s]; sp[tid] += sp[tid + s]; }
        __syncthreads();
    }
    if (tid == 0) {
        out[0] = sl[0] * (1.0f / NROWS);
        if (out_size > 1) out[1] = sp[0] * (1.0f / NROWS);
    }
}

// ---------------------------------------------------------------------------
extern "C" void kernel_launch(void* const* d_in, const int* in_sizes, int n_in,
                              void* d_out, int out_size)
{
    const float* x   = (const float*)d_in[0];
    const void*  tgt = d_in[1];
    float*       out = (float*)d_out;

    cudaFuncSetAttribute(tile_kernel, cudaFuncAttributeMaxDynamicSharedMemorySize, SMEM_TOTAL);

    init_kernel<<<1, 1>>>();
    prep_kernel<<<NROWS / 8, 256>>>(x, (const int*)tgt);
    convert_kernel<<<NROWS / 256, 256>>>(tgt);

    dim3 grid(NROWS / BN, NROWS / BM);   // (64, 64); lower triangle exits early
    tile_kernel<<<grid, 256, SMEM_TOTAL>>>();

    final_kernel<<<1, 256>>>(out, out_size);
}

// round 16
// speedup vs baseline: 1.7861x; 1.2771x over previous
#include <cuda_runtime.h>
#include <cuda_fp16.h>
#include <math.h>
#include <stdint.h>

#define NROWS 8192
#define DDIM  256
#define MARGIN 0.3f

#define BM 128
#define BN 128
#define KC  64
#define NSTAGE (DDIM / KC)   // 4

// ---- dynamic smem layout ----
#define OFF_SQA 0
#define OFF_TA  512
#define OFF_SQB 1024
#define OFF_TB  1536
#define OFF_APR 2048
#define OFF_ANR 2560
#define OFF_APC 3072
#define OFF_ANC 3584
#define OFF_TILE 4096
// per stage: A 128 rows x 128B = 16KB ; B 128 rows x 128B = 16KB
#define STAGE_BYTES 32768
#define A_OFF 0
#define B_OFF 16384
#define SMEM_TOTAL (OFF_TILE + 2 * STAGE_BYTES)   // 69632 -> 2 CTAs/SM

// ---- device globals (no allocation allowed) ----
__device__ float        g_sq[NROWS];
__device__ unsigned int g_ap[NROWS];
__device__ unsigned int g_an[NROWS];
__device__ int          g_tgt[NROWS];
__device__ int          g_is32;
__device__ uint4        g_xh4[NROWS * DDIM / 8];   // fp16(x), 8 per uint4

// ---- helpers ----
static __device__ __forceinline__ uint32_t smem_u32(const void* p) {
    uint32_t a;
    asm("{ .reg .u64 t; cvta.to.shared.u64 t, %1; cvt.u32.u64 %0, t; }" : "=r"(a) : "l"(p));
    return a;
}
static __device__ __forceinline__ void cp16(uint32_t saddr, const void* g) {
    asm volatile("cp.async.cg.shared.global [%0], [%1], 16;" :: "r"(saddr), "l"(g));
}
#define CP_COMMIT() asm volatile("cp.async.commit_group;" ::: "memory")
#define CP_WAIT(n)  asm volatile("cp.async.wait_group %0;" :: "n"(n) : "memory")

static __device__ __forceinline__ void ldsm4(uint32_t a, uint32_t* r) {
    asm volatile("ldmatrix.sync.aligned.m8n8.x4.shared.b16 {%0,%1,%2,%3}, [%4];"
                 : "=r"(r[0]), "=r"(r[1]), "=r"(r[2]), "=r"(r[3]) : "r"(a));
}
static __device__ __forceinline__ void mma16816(float* d, const uint32_t* a, const uint32_t* b) {
    asm volatile("mma.sync.aligned.m16n8k16.row.col.f32.f16.f16.f32 "
                 "{%0,%1,%2,%3}, {%4,%5,%6,%7}, {%8,%9}, {%0,%1,%2,%3};"
                 : "+f"(d[0]), "+f"(d[1]), "+f"(d[2]), "+f"(d[3])
                 : "r"(a[0]), "r"(a[1]), "r"(a[2]), "r"(a[3]), "r"(b[0]), "r"(b[1]));
}
// swizzle: 128B rows, 16B chunk index 0-7 XOR (row&7)
static __device__ __forceinline__ uint32_t swz(int r, int chunk) {
    return (uint32_t)((r << 7) + ((chunk ^ (r & 7)) << 4));
}

// ---------------------------------------------------------------------------
__global__ void init_kernel() { g_is32 = 0; }

// norms + reduction init + dtype detect + fp16 convert
__global__ void prep_kernel(const float* __restrict__ x, const int* __restrict__ t32)
{
    int row  = blockIdx.x * 8 + (threadIdx.x >> 5);
    int lane = threadIdx.x & 31;
    const float* xr = x + (size_t)row * DDIM;
    __half* xh = (__half*)g_xh4;
    float s = 0.f;
#pragma unroll
    for (int k = lane; k < DDIM; k += 32) {
        float v = xr[k];
        s = fmaf(v, v, s);
        xh[(size_t)row * DDIM + k] = __float2half_rn(v);
    }
#pragma unroll
    for (int o = 16; o; o >>= 1) s += __shfl_xor_sync(0xffffffffu, s, o);
    if (lane == 0) {
        g_sq[row] = s;
        g_ap[row] = 0u;
        g_an[row] = 0x7f800000u;
        if (row < 2048 && t32[2 * row + 1] != 0) atomicOr(&g_is32, 1);
    }
}

__global__ void convert_kernel(const void* __restrict__ tgt)
{
    int i = blockIdx.x * 256 + threadIdx.x;
    if (i < NROWS) {
        if (g_is32) g_tgt[i] = ((const int*)tgt)[i];
        else        g_tgt[i] = (int)((const long long*)tgt)[i];
    }
}

// ---------------------------------------------------------------------------
// Fused HMMA (mma.sync fp16, single product) + dist + dual row/col reduction.
// Upper-triangular blocks only; cp.async double-buffered; KC=64.
// ---------------------------------------------------------------------------
__global__ __launch_bounds__(256, 2)
void tile_kernel()
{
    const int bx = blockIdx.x;
    const int by = blockIdx.y;
    if (by > bx) return;
    const bool diag = (bx == by);

    extern __shared__ char sm[];
    const uint32_t sb = smem_u32(sm);

    const int tid  = threadIdx.x;
    const int lane = tid & 31;
    const int wid  = tid >> 5;
    const int wm   = wid & 1;     // 2 warps over M (64 rows each)
    const int wn   = wid >> 1;    // 4 warps over N (32 cols each)
    const int r0   = by * BM;
    const int c0   = bx * BN;

    // ---- stage 0 loads: 8 cp16/thread (4 A + 4 B) ----
    {
        uint32_t base = sb + OFF_TILE;
#pragma unroll
        for (int t = 0; t < 4; t++) {
            int idx = tid + t * 256;
            int r = idx >> 3, c = idx & 7;
            uint32_t so = swz(r, c);
            cp16(base + A_OFF + so, &g_xh4[(r0 + r) * (DDIM / 8) + c]);
            cp16(base + B_OFF + so, &g_xh4[(c0 + r) * (DDIM / 8) + c]);
        }
        CP_COMMIT();
    }

    // ---- metadata into smem ----
    if (tid < 128) {
        ((float*)(sm + OFF_SQA))[tid]    = g_sq[r0 + tid];
        ((int*)(sm + OFF_TA))[tid]       = g_tgt[r0 + tid];
        ((float*)(sm + OFF_SQB))[tid]    = g_sq[c0 + tid];
        ((int*)(sm + OFF_TB))[tid]       = g_tgt[c0 + tid];
        ((uint32_t*)(sm + OFF_APR))[tid] = 0u;
        ((uint32_t*)(sm + OFF_ANR))[tid] = 0x7f800000u;
        ((uint32_t*)(sm + OFF_APC))[tid] = 0u;
        ((uint32_t*)(sm + OFF_ANC))[tid] = 0x7f800000u;
    }

    float acc[4][4][4];
#pragma unroll
    for (int i = 0; i < 4; i++)
#pragma unroll
        for (int j = 0; j < 4; j++)
#pragma unroll
            for (int q = 0; q < 4; q++) acc[i][j][q] = 0.f;

    // ---- mainloop over 4 K chunks of 64 ----
#pragma unroll 1
    for (int s = 0; s < NSTAGE; s++) {
        if (s + 1 < NSTAGE) {
            const int sn = s + 1;
            uint32_t base = sb + OFF_TILE + (sn & 1) * STAGE_BYTES;
#pragma unroll
            for (int t = 0; t < 4; t++) {
                int idx = tid + t * 256;
                int r = idx >> 3, c = idx & 7;
                uint32_t so = swz(r, c);
                cp16(base + A_OFF + so, &g_xh4[(r0 + r) * (DDIM / 8) + sn * 8 + c]);
                cp16(base + B_OFF + so, &g_xh4[(c0 + r) * (DDIM / 8) + sn * 8 + c]);
            }
            CP_COMMIT();
            CP_WAIT(1);
        } else {
            CP_WAIT(0);
        }
        __syncthreads();

        const uint32_t base = sb + OFF_TILE + (s & 1) * STAGE_BYTES;
#pragma unroll
        for (int st = 0; st < 4; st++) {      // 4 k-steps of 16 per chunk
            uint32_t bh[2][4];
            const int rB0 = wn * 32 + ((lane >> 4) << 3) + (lane & 7);
            const int cB  = st * 2 + ((lane >> 3) & 1);
#pragma unroll
            for (int jp = 0; jp < 2; jp++)
                ldsm4(base + B_OFF + swz(rB0 + jp * 16, cB), bh[jp]);

            const int rA0 = wm * 64 + (lane & 15);
            const int cA  = st * 2 + (lane >> 4);
#pragma unroll
            for (int i = 0; i < 4; i++) {
                uint32_t ah[4];
                ldsm4(base + A_OFF + swz(rA0 + i * 16, cA), ah);
#pragma unroll
                for (int j = 0; j < 4; j++)
                    mma16816(acc[i][j], ah, &bh[j >> 1][(j & 1) * 2]);
            }
        }
        __syncthreads();
    }

    // ---- epilogue ----
    const int gid = lane >> 2;
    const int tg  = lane & 3;
    const float* sqA = (const float*)(sm + OFF_SQA);
    const float* sqB = (const float*)(sm + OFF_SQB);
    const int*   tA  = (const int*)(sm + OFF_TA);
    const int*   tB  = (const int*)(sm + OFF_TB);

    float apR[8], anR[8], apC[8], anC[8];
#pragma unroll
    for (int q = 0; q < 8; q++) { apR[q] = 0.f; anR[q] = INFINITY; apC[q] = 0.f; anC[q] = INFINITY; }

#pragma unroll
    for (int i = 0; i < 4; i++) {
#pragma unroll
        for (int h = 0; h < 2; h++) {
            const int r   = wm * 64 + i * 16 + h * 8 + gid;
            const float sqr = sqA[r];
            const int   tr  = tA[r];
#pragma unroll
            for (int j = 0; j < 4; j++) {
#pragma unroll
                for (int e = 0; e < 2; e++) {
                    const int c   = wn * 32 + j * 8 + 2 * tg + e;
                    float dot  = acc[i][j][h * 2 + e];
                    float d2   = sqr + sqB[c] - 2.f * dot;
                    float dist = sqrtf(fmaxf(d2, 1e-12f));
                    if (tr == tB[c]) {
                        apR[i * 2 + h] = fmaxf(apR[i * 2 + h], dist);
                        apC[j * 2 + e] = fmaxf(apC[j * 2 + e], dist);
                    } else {
                        anR[i * 2 + h] = fminf(anR[i * 2 + h], dist);
                        anC[j * 2 + e] = fminf(anC[j * 2 + e], dist);
                    }
                }
            }
        }
    }

    // row-side: reduce over tg (lanes xor 1,2), then smem atomic per row
#pragma unroll
    for (int q = 0; q < 8; q++) {
#pragma unroll
        for (int o = 1; o <= 2; o <<= 1) {
            apR[q] = fmaxf(apR[q], __shfl_xor_sync(0xffffffffu, apR[q], o));
            anR[q] = fminf(anR[q], __shfl_xor_sync(0xffffffffu, anR[q], o));
        }
        if (tg == 0) {
            const int i = q >> 1, h = q & 1;
            const int r = wm * 64 + i * 16 + h * 8 + gid;
            atomicMax((unsigned int*)(sm + OFF_APR) + r, __float_as_uint(apR[q]));
            atomicMin((unsigned int*)(sm + OFF_ANR) + r, __float_as_uint(anR[q]));
        }
    }
    // col-side: reduce over gid (lanes xor 4,8,16), then smem atomic per col
#pragma unroll
    for (int q = 0; q < 8; q++) {
#pragma unroll
        for (int o = 4; o <= 16; o <<= 1) {
            apC[q] = fmaxf(apC[q], __shfl_xor_sync(0xffffffffu, apC[q], o));
            anC[q] = fminf(anC[q], __shfl_xor_sync(0xffffffffu, anC[q], o));
        }
        if (gid == 0) {
            const int j = q >> 1, e = q & 1;
            const int c = wn * 32 + j * 8 + 2 * tg + e;
            atomicMax((unsigned int*)(sm + OFF_APC) + c, __float_as_uint(apC[q]));
            atomicMin((unsigned int*)(sm + OFF_ANC) + c, __float_as_uint(anC[q]));
        }
    }
    __syncthreads();

    if (tid < 128) {
        atomicMax(&g_ap[r0 + tid], ((unsigned int*)(sm + OFF_APR))[tid]);
        atomicMin(&g_an[r0 + tid], ((unsigned int*)(sm + OFF_ANR))[tid]);
        if (!diag) {
            atomicMax(&g_ap[c0 + tid], ((unsigned int*)(sm + OFF_APC))[tid]);
            atomicMin(&g_an[c0 + tid], ((unsigned int*)(sm + OFF_ANC))[tid]);
        }
    }
}

// ---------------------------------------------------------------------------
__global__ void final_kernel(float* __restrict__ out, int out_size)
{
    __shared__ float sl[256];
    __shared__ float sp[256];
    int tid = threadIdx.x;
    float loss = 0.f, prec = 0.f;
    for (int r = tid; r < NROWS; r += 256) {
        float ap = __uint_as_float(g_ap[r]);
        float an = __uint_as_float(g_an[r]);
        loss += fmaxf(ap - an + MARGIN, 0.f);
        prec += (an > ap) ? 1.f : 0.f;
    }
    sl[tid] = loss;
    sp[tid] = prec;
    __syncthreads();
    for (int s = 128; s; s >>= 1) {
        if (tid < s) { sl[tid] += sl[tid + s]; sp[tid] += sp[tid + s]; }
        __syncthreads();
    }
    if (tid == 0) {
        out[0] = sl[0] * (1.0f / NROWS);
        if (out_size > 1) out[1] = sp[0] * (1.0f / NROWS);
    }
}

// ---------------------------------------------------------------------------
extern "C" void kernel_launch(void* const* d_in, const int* in_sizes, int n_in,
                              void* d_out, int out_size)
{
    const float* x   = (const float*)d_in[0];
    const void*  tgt = d_in[1];
    float*       out = (float*)d_out;

    cudaFuncSetAttribute(tile_kernel, cudaFuncAttributeMaxDynamicSharedMemorySize, SMEM_TOTAL);

    init_kernel<<<1, 1>>>();
    prep_kernel<<<NROWS / 8, 256>>>(x, (const int*)tgt);
    convert_kernel<<<NROWS / 256, 256>>>(tgt);

    dim3 grid(NROWS / BN, NROWS / BM);   // (64, 64); lower triangle exits early
    tile_kernel<<<grid, 256, SMEM_TOTAL>>>();

    final_kernel<<<1, 256>>>(out, out_size);
}

// round 17
// speedup vs baseline: 1.9193x; 1.0745x over previous
#include <cuda_runtime.h>
#include <cuda_fp16.h>
#include <math.h>
#include <stdint.h>

#define NROWS 8192
#define DDIM  256
#define MARGIN 0.3f

#define BM 128
#define BN 128
#define KC  64
#define NSTAGE (DDIM / KC)   // 4

// ---- dynamic smem layout ----
#define OFF_SQA 0
#define OFF_TA  512
#define OFF_SQB 1024
#define OFF_TB  1536
#define OFF_APR 2048
#define OFF_ANR 2560
#define OFF_APC 3072
#define OFF_ANC 3584
#define OFF_TILE 4096
#define STAGE_BYTES 32768     // A 128x128B + B 128x128B
#define A_OFF 0
#define B_OFF 16384
#define SMEM_TOTAL (OFF_TILE + 2 * STAGE_BYTES)   // 69632 -> 2 CTAs/SM

// ---- device globals (no allocation allowed) ----
__device__ float        g_sq[NROWS];
__device__ unsigned int g_ap[NROWS];
__device__ unsigned int g_an[NROWS];
__device__ int          g_tgt[NROWS];
__device__ uint4        g_xh4[NROWS * DDIM / 8];   // fp16(x), 8 per uint4

// ---- helpers ----
static __device__ __forceinline__ uint32_t smem_u32(const void* p) {
    uint32_t a;
    asm("{ .reg .u64 t; cvta.to.shared.u64 t, %1; cvt.u32.u64 %0, t; }" : "=r"(a) : "l"(p));
    return a;
}
static __device__ __forceinline__ void cp16(uint32_t saddr, const void* g) {
    asm volatile("cp.async.cg.shared.global [%0], [%1], 16;" :: "r"(saddr), "l"(g));
}
#define CP_COMMIT() asm volatile("cp.async.commit_group;" ::: "memory")
#define CP_WAIT(n)  asm volatile("cp.async.wait_group %0;" :: "n"(n) : "memory")

static __device__ __forceinline__ void ldsm4(uint32_t a, uint32_t* r) {
    asm volatile("ldmatrix.sync.aligned.m8n8.x4.shared.b16 {%0,%1,%2,%3}, [%4];"
                 : "=r"(r[0]), "=r"(r[1]), "=r"(r[2]), "=r"(r[3]) : "r"(a));
}
static __device__ __forceinline__ void mma16816(float* d, const uint32_t* a, const uint32_t* b) {
    asm volatile("mma.sync.aligned.m16n8k16.row.col.f32.f16.f16.f32 "
                 "{%0,%1,%2,%3}, {%4,%5,%6,%7}, {%8,%9}, {%0,%1,%2,%3};"
                 : "+f"(d[0]), "+f"(d[1]), "+f"(d[2]), "+f"(d[3])
                 : "r"(a[0]), "r"(a[1]), "r"(a[2]), "r"(a[3]), "r"(b[0]), "r"(b[1]));
}
// swizzle: 128B rows, 16B chunk index 0-7 XOR (row&7)
static __device__ __forceinline__ uint32_t swz(int r, int chunk) {
    return (uint32_t)((r << 7) + ((chunk ^ (r & 7)) << 4));
}

// ---------------------------------------------------------------------------
// prep: norms + reduction init + fp16 convert (no dtype logic here)
__global__ void prep_kernel(const float* __restrict__ x)
{
    int row  = blockIdx.x * 8 + (threadIdx.x >> 5);
    int lane = threadIdx.x & 31;
    const float* xr = x + (size_t)row * DDIM;
    __half* xh = (__half*)g_xh4;
    float s = 0.f;
#pragma unroll
    for (int k = lane; k < DDIM; k += 32) {
        float v = xr[k];
        s = fmaf(v, v, s);
        xh[(size_t)row * DDIM + k] = __float2half_rn(v);
    }
#pragma unroll
    for (int o = 16; o; o >>= 1) s += __shfl_xor_sync(0xffffffffu, s, o);
    if (lane == 0) {
        g_sq[row] = s;
        g_ap[row] = 0u;
        g_an[row] = 0x7f800000u;
    }
}

// convert: dtype-robust targets. Every block deterministically scans the SAME
// first 2048 odd 32-bit words (in-bounds for both int32[8192] and int64[8192])
// to decide the dtype, then converts its slice. No cross-block state.
__global__ void convert_kernel(const void* __restrict__ tgt)
{
    __shared__ int s_is32;
    const int tid = threadIdx.x;
    if (tid == 0) s_is32 = 0;
    __syncthreads();
    const int* t32 = (const int*)tgt;
    int v = 0;
#pragma unroll
    for (int k = 0; k < 8; k++) v |= t32[2 * (tid + k * 256) + 1];
    if (v) atomicOr(&s_is32, 1);
    __syncthreads();
    const int is32 = s_is32;

    int i = blockIdx.x * 256 + tid;
    if (i < NROWS) {
        if (is32) g_tgt[i] = t32[i];
        else      g_tgt[i] = (int)((const long long*)tgt)[i];
    }
}

// ---------------------------------------------------------------------------
// Fused HMMA (fp16 single product) + dist + dual row/col reduction.
// Upper-triangular blocks; cp.async double buffer; register-pipelined frags.
// ---------------------------------------------------------------------------
__global__ __launch_bounds__(256, 2)
void tile_kernel()
{
    const int bx = blockIdx.x;
    const int by = blockIdx.y;
    if (by > bx) return;
    const bool diag = (bx == by);

    extern __shared__ char sm[];
    const uint32_t sb = smem_u32(sm);

    const int tid  = threadIdx.x;
    const int lane = tid & 31;
    const int wid  = tid >> 5;
    const int wm   = wid & 1;     // 2 warps over M (64 rows each)
    const int wn   = wid >> 1;    // 4 warps over N (32 cols each)
    const int r0   = by * BM;
    const int c0   = bx * BN;

    // ---- stage 0 loads: 8 cp16/thread (4 A + 4 B) ----
    {
        uint32_t base = sb + OFF_TILE;
#pragma unroll
        for (int t = 0; t < 4; t++) {
            int idx = tid + t * 256;
            int r = idx >> 3, c = idx & 7;
            uint32_t so = swz(r, c);
            cp16(base + A_OFF + so, &g_xh4[(r0 + r) * (DDIM / 8) + c]);
            cp16(base + B_OFF + so, &g_xh4[(c0 + r) * (DDIM / 8) + c]);
        }
        CP_COMMIT();
    }

    // ---- metadata into smem ----
    if (tid < 128) {
        ((float*)(sm + OFF_SQA))[tid]    = g_sq[r0 + tid];
        ((int*)(sm + OFF_TA))[tid]       = g_tgt[r0 + tid];
        ((float*)(sm + OFF_SQB))[tid]    = g_sq[c0 + tid];
        ((int*)(sm + OFF_TB))[tid]       = g_tgt[c0 + tid];
        ((uint32_t*)(sm + OFF_APR))[tid] = 0u;
        ((uint32_t*)(sm + OFF_ANR))[tid] = 0x7f800000u;
        ((uint32_t*)(sm + OFF_APC))[tid] = 0u;
        ((uint32_t*)(sm + OFF_ANC))[tid] = 0x7f800000u;
    }

    float acc[4][4][4];
#pragma unroll
    for (int i = 0; i < 4; i++)
#pragma unroll
        for (int j = 0; j < 4; j++)
#pragma unroll
            for (int q = 0; q < 4; q++) acc[i][j][q] = 0.f;

    const int rB0 = wn * 32 + ((lane >> 4) << 3) + (lane & 7);
    const int rA0 = wm * 64 + (lane & 15);
    const int cb  = (lane >> 3) & 1;   // B chunk parity
    const int ca  = lane >> 4;         // A chunk parity

    // ---- mainloop over 4 K chunks of 64 ----
#pragma unroll 1
    for (int s = 0; s < NSTAGE; s++) {
        if (s + 1 < NSTAGE) {
            const int sn = s + 1;
            uint32_t base = sb + OFF_TILE + (sn & 1) * STAGE_BYTES;
#pragma unroll
            for (int t = 0; t < 4; t++) {
                int idx = tid + t * 256;
                int r = idx >> 3, c = idx & 7;
                uint32_t so = swz(r, c);
                cp16(base + A_OFF + so, &g_xh4[(r0 + r) * (DDIM / 8) + sn * 8 + c]);
                cp16(base + B_OFF + so, &g_xh4[(c0 + r) * (DDIM / 8) + sn * 8 + c]);
            }
            CP_COMMIT();
            CP_WAIT(1);
        } else {
            CP_WAIT(0);
        }
        __syncthreads();

        const uint32_t base = sb + OFF_TILE + (s & 1) * STAGE_BYTES;

        // register-pipelined fragments: bh[2 bufs][2 jp][4], ah[2 bufs][4]
        uint32_t bh[2][2][4], ah[2][4];
        ldsm4(base + B_OFF + swz(rB0,      cb), bh[0][0]);
        ldsm4(base + B_OFF + swz(rB0 + 16, cb), bh[0][1]);
        ldsm4(base + A_OFF + swz(rA0,      ca), ah[0]);

#pragma unroll
        for (int st = 0; st < 4; st++) {
            const int bcur = st & 1;
#pragma unroll
            for (int i = 0; i < 4; i++) {
                const int g    = st * 4 + i;
                const int acur = g & 1;
                if (g + 1 < 16) {
                    const int gn  = g + 1;
                    const int stn = gn >> 2, in = gn & 3;
                    ldsm4(base + A_OFF + swz(rA0 + in * 16, stn * 2 + ca), ah[acur ^ 1]);
                }
                if (i == 1 && st < 3) {
                    ldsm4(base + B_OFF + swz(rB0,      (st + 1) * 2 + cb), bh[bcur ^ 1][0]);
                    ldsm4(base + B_OFF + swz(rB0 + 16, (st + 1) * 2 + cb), bh[bcur ^ 1][1]);
                }
#pragma unroll
                for (int j = 0; j < 4; j++)
                    mma16816(acc[i][j], ah[acur], &bh[bcur][j >> 1][(j & 1) * 2]);
            }
        }
        __syncthreads();
    }

    // ---- epilogue ----
    const int gid = lane >> 2;
    const int tg  = lane & 3;
    const float* sqA = (const float*)(sm + OFF_SQA);
    const float* sqB = (const float*)(sm + OFF_SQB);
    const int*   tA  = (const int*)(sm + OFF_TA);
    const int*   tB  = (const int*)(sm + OFF_TB);

    float apR[8], anR[8], apC[8], anC[8];
#pragma unroll
    for (int q = 0; q < 8; q++) { apR[q] = 0.f; anR[q] = INFINITY; apC[q] = 0.f; anC[q] = INFINITY; }

#pragma unroll
    for (int i = 0; i < 4; i++) {
#pragma unroll
        for (int h = 0; h < 2; h++) {
            const int r   = wm * 64 + i * 16 + h * 8 + gid;
            const float sqr = sqA[r];
            const int   tr  = tA[r];
#pragma unroll
            for (int j = 0; j < 4; j++) {
#pragma unroll
                for (int e = 0; e < 2; e++) {
                    const int c   = wn * 32 + j * 8 + 2 * tg + e;
                    float dot  = acc[i][j][h * 2 + e];
                    float d2   = sqr + sqB[c] - 2.f * dot;
                    float dist = sqrtf(fmaxf(d2, 1e-12f));
                    if (tr == tB[c]) {
                        apR[i * 2 + h] = fmaxf(apR[i * 2 + h], dist);
                        apC[j * 2 + e] = fmaxf(apC[j * 2 + e], dist);
                    } else {
                        anR[i * 2 + h] = fminf(anR[i * 2 + h], dist);
                        anC[j * 2 + e] = fminf(anC[j * 2 + e], dist);
                    }
                }
            }
        }
    }

    // row-side: reduce over tg (lanes xor 1,2), then smem atomic per row
#pragma unroll
    for (int q = 0; q < 8; q++) {
#pragma unroll
        for (int o = 1; o <= 2; o <<= 1) {
            apR[q] = fmaxf(apR[q], __shfl_xor_sync(0xffffffffu, apR[q], o));
            anR[q] = fminf(anR[q], __shfl_xor_sync(0xffffffffu, anR[q], o));
        }
        if (tg == 0) {
            const int i = q >> 1, h = q & 1;
            const int r = wm * 64 + i * 16 + h * 8 + gid;
            atomicMax((unsigned int*)(sm + OFF_APR) + r, __float_as_uint(apR[q]));
            atomicMin((unsigned int*)(sm + OFF_ANR) + r, __float_as_uint(anR[q]));
        }
    }
    // col-side: reduce over gid (lanes xor 4,8,16), then smem atomic per col
#pragma unroll
    for (int q = 0; q < 8; q++) {
#pragma unroll
        for (int o = 4; o <= 16; o <<= 1) {
            apC[q] = fmaxf(apC[q], __shfl_xor_sync(0xffffffffu, apC[q], o));
            anC[q] = fminf(anC[q], __shfl_xor_sync(0xffffffffu, anC[q], o));
        }
        if (gid == 0) {
            const int j = q >> 1, e = q & 1;
            const int c = wn * 32 + j * 8 + 2 * tg + e;
            atomicMax((unsigned int*)(sm + OFF_APC) + c, __float_as_uint(apC[q]));
            atomicMin((unsigned int*)(sm + OFF_ANC) + c, __float_as_uint(anC[q]));
        }
    }
    __syncthreads();

    if (tid < 128) {
        atomicMax(&g_ap[r0 + tid], ((unsigned int*)(sm + OFF_APR))[tid]);
        atomicMin(&g_an[r0 + tid], ((unsigned int*)(sm + OFF_ANR))[tid]);
        if (!diag) {
            atomicMax(&g_ap[c0 + tid], ((unsigned int*)(sm + OFF_APC))[tid]);
            atomicMin(&g_an[c0 + tid], ((unsigned int*)(sm + OFF_ANC))[tid]);
        }
    }
}

// ---------------------------------------------------------------------------
__global__ void final_kernel(float* __restrict__ out, int out_size)
{
    __shared__ float sl[1024];
    __shared__ float sp[1024];
    int tid = threadIdx.x;
    float loss = 0.f, prec = 0.f;
#pragma unroll
    for (int r = tid; r < NROWS; r += 1024) {
        float ap = __uint_as_float(g_ap[r]);
        float an = __uint_as_float(g_an[r]);
        loss += fmaxf(ap - an + MARGIN, 0.f);
        prec += (an > ap) ? 1.f : 0.f;
    }
    sl[tid] = loss;
    sp[tid] = prec;
    __syncthreads();
    for (int s = 512; s; s >>= 1) {
        if (tid < s) { sl[tid] += sl[tid + s]; sp[tid] += sp[tid + s]; }
        __syncthreads();
    }
    if (tid == 0) {
        out[0] = sl[0] * (1.0f / NROWS);
        if (out_size > 1) out[1] = sp[0] * (1.0f / NROWS);
    }
}

// ---------------------------------------------------------------------------
extern "C" void kernel_launch(void* const* d_in, const int* in_sizes, int n_in,
                              void* d_out, int out_size)
{
    const float* x   = (const float*)d_in[0];
    const void*  tgt = d_in[1];
    float*       out = (float*)d_out;

    cudaFuncSetAttribute(tile_kernel, cudaFuncAttributeMaxDynamicSharedMemorySize, SMEM_TOTAL);

    prep_kernel<<<NROWS / 8, 256>>>(x);
    convert_kernel<<<NROWS / 256, 256>>>(tgt);

    dim3 grid(NROWS / BN, NROWS / BM);   // (64, 64); lower triangle exits early
    tile_kernel<<<grid, 256, SMEM_TOTAL>>>();

    final_kernel<<<1, 1024>>>(out, out_size);
}